// round 1
// baseline (speedup 1.0000x reference)
#include <cuda_runtime.h>
#include <math.h>
#include <stdint.h>

#define BB   8
#define NN   4096
#define SS   1024
#define KNBR 16
#define CIN  128
#define COUT 256
#define MROWS (BB*SS*KNBR)   /* 131072 */
#define BSR   (BB*SS)        /* 8192  */

// ---------------- static device scratch (no allocs allowed) ----------------
__device__ float g_buf1[(size_t)MROWS*COUT];  // Kmat -> a1 -> att
__device__ float g_buf2[(size_t)MROWS*COUT];  // Vmat
__device__ float g_buf3[(size_t)MROWS*COUT];  // pos_enc
__device__ float g_buf4[(size_t)MROWS*COUT];  // h1 -> h2
__device__ float g_q   [(size_t)BSR*COUT];
__device__ float g_res0[(size_t)BSR*COUT];
__device__ float g_res1[(size_t)BSR*COUT];
__device__ int   g_fps [BSR];
__device__ int   g_knn [MROWS];
__device__ float g_psum[64*COUT];
__device__ float g_psq [64*COUT];
__device__ float g_scale[COUT];
__device__ float g_shift[COUT];

// ---------------------------- FPS -----------------------------------------
// one block per batch; 1024 threads x 4 points each, points in registers.
__global__ __launch_bounds__(1024) void fps_kernel(const float* __restrict__ xyz,
                                                   float* __restrict__ newxyz)
{
    int b   = blockIdx.x;
    int tid = threadIdx.x;
    const float* base = xyz + (size_t)b * NN * 3;

    float px[4], py[4], pz[4], dist[4];
#pragma unroll
    for (int j = 0; j < 4; j++) {
        int i = tid * 4 + j;
        px[j] = base[i*3+0]; py[j] = base[i*3+1]; pz[j] = base[i*3+2];
        dist[j] = 1e10f;
    }

    __shared__ float swv[32];
    __shared__ int   swi[32];
    __shared__ int   sfar;

    int far  = 0;
    int lane = tid & 31, wid = tid >> 5;

    for (int s = 0; s < SS; s++) {
        float cx = __ldg(base + far*3 + 0);
        float cy = __ldg(base + far*3 + 1);
        float cz = __ldg(base + far*3 + 2);
        if (tid == 0) {
            g_fps[b*SS + s] = b*NN + far;
            newxyz[((size_t)b*SS + s)*3 + 0] = cx;
            newxyz[((size_t)b*SS + s)*3 + 1] = cy;
            newxyz[((size_t)b*SS + s)*3 + 2] = cz;
        }
        float bv = -1.0f; int bi = 0;
#pragma unroll
        for (int j = 0; j < 4; j++) {
            float dx = __fsub_rn(px[j], cx);
            float dy = __fsub_rn(py[j], cy);
            float dz = __fsub_rn(pz[j], cz);
            float d  = __fadd_rn(__fadd_rn(__fmul_rn(dx,dx), __fmul_rn(dy,dy)),
                                 __fmul_rn(dz,dz));
            dist[j] = fminf(dist[j], d);
            if (dist[j] > bv) { bv = dist[j]; bi = tid*4 + j; }   // ascending i -> lowest idx on tie
        }
#pragma unroll
        for (int off = 16; off; off >>= 1) {
            float ov = __shfl_xor_sync(0xffffffffu, bv, off);
            int   oi = __shfl_xor_sync(0xffffffffu, bi, off);
            if (ov > bv || (ov == bv && oi < bi)) { bv = ov; bi = oi; }
        }
        if (lane == 0) { swv[wid] = bv; swi[wid] = bi; }
        __syncthreads();
        if (tid < 32) {
            bv = swv[tid]; bi = swi[tid];
#pragma unroll
            for (int off = 16; off; off >>= 1) {
                float ov = __shfl_xor_sync(0xffffffffu, bv, off);
                int   oi = __shfl_xor_sync(0xffffffffu, bi, off);
                if (ov > bv || (ov == bv && oi < bi)) { bv = ov; bi = oi; }
            }
            if (tid == 0) sfar = bi;
        }
        __syncthreads();
        far = sfar;
    }
}

// ---------------------------- KNN -----------------------------------------
// one warp per sampled point: register-sorted top-16, shared-memory merge.
__global__ __launch_bounds__(256) void knn_kernel(const float* __restrict__ xyz,
                                                  const float* __restrict__ newxyz)
{
    int warp = (blockIdx.x * blockDim.x + threadIdx.x) >> 5;  // 0..8191
    int lane = threadIdx.x & 31;
    int wloc = threadIdx.x >> 5;
    int b = warp / SS;
    const float* base = xyz + (size_t)b * NN * 3;

    float nx = newxyz[(size_t)warp*3+0];
    float ny = newxyz[(size_t)warp*3+1];
    float nz = newxyz[(size_t)warp*3+2];
    float ns = fmaf(nz, nz, fmaf(ny, ny, __fmul_rn(nx, nx)));

    float v[16]; int id[16];
#pragma unroll
    for (int t = 0; t < 16; t++) { v[t] = 3.4e38f; id[t] = 0x7fffffff; }

    for (int j = lane; j < NN; j += 32) {
        float x = base[j*3+0], y = base[j*3+1], z = base[j*3+2];
        float dot = fmaf(z, nz, fmaf(y, ny, __fmul_rn(x, nx)));
        float nq  = fmaf(z, z,  fmaf(y, y,  __fmul_rn(x, x)));
        float d   = __fadd_rn(__fsub_rn(ns, __fmul_rn(2.0f, dot)), nq);
        if (d < v[15]) {
            v[15] = d; id[15] = j;
#pragma unroll
            for (int t = 15; t > 0; t--) {
                if (v[t] < v[t-1] || (v[t] == v[t-1] && id[t] < id[t-1])) {
                    float tv = v[t]; v[t] = v[t-1]; v[t-1] = tv;
                    int   ti = id[t]; id[t] = id[t-1]; id[t-1] = ti;
                } else break;
            }
        }
    }

    __shared__ float smd[8][512];
    __shared__ int   smi[8][512];
#pragma unroll
    for (int t = 0; t < 16; t++) {
        smd[wloc][lane*16 + t] = v[t];
        smi[wloc][lane*16 + t] = id[t];
    }
    __syncwarp();

    int p = 0;
    for (int t = 0; t < 16; t++) {
        float cv = (p < 16) ? smd[wloc][lane*16 + p] : 3.4e38f;
        int   ci = (p < 16) ? smi[wloc][lane*16 + p] : 0x7fffffff;
        float mv = cv; int mi = ci;
#pragma unroll
        for (int off = 16; off; off >>= 1) {
            float ov = __shfl_xor_sync(0xffffffffu, mv, off);
            int   oi = __shfl_xor_sync(0xffffffffu, mi, off);
            if (ov < mv || (ov == mv && oi < mi)) { mv = ov; mi = oi; }
        }
        if (cv == mv && ci == mi) p++;
        if (lane == 0) g_knn[(size_t)warp*16 + t] = b*NN + mi;
        __syncwarp();
    }
}

// ------------------------ generic fp32 tiled GEMM --------------------------
// C[M,N] = gather(A)[M,K] @ W[K,N] (+bias) (+relu). 128x128x16 tiles, 256 thr.
__global__ __launch_bounds__(256) void sgemm_k(
    const float* __restrict__ A, const int* __restrict__ rowmap,
    const float* __restrict__ W, const float* __restrict__ bias,
    float* __restrict__ C, int M, int Kd, int N, int relu)
{
    __shared__ float As[16][132];   // transposed, padded
    __shared__ float Bs[16][128];
    __shared__ int   rmap[128];

    int tid = threadIdx.x;
    int m0  = blockIdx.y * 128;
    int n0  = blockIdx.x * 128;

    if (tid < 128) rmap[tid] = rowmap ? rowmap[m0 + tid] : (m0 + tid);
    __syncthreads();

    float acc[8][8];
#pragma unroll
    for (int i = 0; i < 8; i++)
#pragma unroll
        for (int j = 0; j < 8; j++) acc[i][j] = 0.0f;

    int tx = tid & 15, ty = tid >> 4;

    for (int k0 = 0; k0 < Kd; k0 += 16) {
#pragma unroll
        for (int l = 0; l < 2; l++) {
            int idx = tid*2 + l;
            int r  = idx >> 2, c4 = idx & 3;
            float4 av = *(const float4*)(A + (size_t)rmap[r]*Kd + k0 + c4*4);
            As[c4*4+0][r] = av.x; As[c4*4+1][r] = av.y;
            As[c4*4+2][r] = av.z; As[c4*4+3][r] = av.w;
        }
#pragma unroll
        for (int l = 0; l < 2; l++) {
            int idx = tid*2 + l;
            int kr = idx >> 5, c = idx & 31;
            *(float4*)(&Bs[kr][c*4]) = *(const float4*)(W + (size_t)(k0+kr)*N + n0 + c*4);
        }
        __syncthreads();
#pragma unroll
        for (int kk = 0; kk < 16; kk++) {
            float a[8], bq[8];
            *(float4*)(a)    = *(float4*)(&As[kk][ty*8]);
            *(float4*)(a+4)  = *(float4*)(&As[kk][ty*8+4]);
            *(float4*)(bq)   = *(float4*)(&Bs[kk][tx*8]);
            *(float4*)(bq+4) = *(float4*)(&Bs[kk][tx*8+4]);
#pragma unroll
            for (int i = 0; i < 8; i++)
#pragma unroll
                for (int j = 0; j < 8; j++) acc[i][j] = fmaf(a[i], bq[j], acc[i][j]);
        }
        __syncthreads();
    }

#pragma unroll
    for (int i = 0; i < 8; i++) {
        int row = m0 + ty*8 + i;
#pragma unroll
        for (int j = 0; j < 8; j += 4) {
            int col = n0 + tx*8 + j;
            float4 o;
            o.x = acc[i][j+0]; o.y = acc[i][j+1]; o.z = acc[i][j+2]; o.w = acc[i][j+3];
            if (bias) { o.x += bias[col]; o.y += bias[col+1]; o.z += bias[col+2]; o.w += bias[col+3]; }
            if (relu) { o.x = fmaxf(o.x,0.f); o.y = fmaxf(o.y,0.f); o.z = fmaxf(o.z,0.f); o.w = fmaxf(o.w,0.f); }
            *(float4*)(C + (size_t)row*N + col) = o;
        }
    }
}

// ------------------ pos-enc layer 1 (3 -> 256, relu) -----------------------
__global__ void h1_kernel(const float* __restrict__ xyz, const float* __restrict__ newxyz,
                          const float* __restrict__ dw1, const float* __restrict__ db1)
{
    int r = blockIdx.x;      // 0..MROWS-1
    int c = threadIdx.x;     // 0..255
    int g  = g_knn[r];
    int bs = r >> 4;
    float cx = xyz[(size_t)g*3+0] - newxyz[(size_t)bs*3+0];
    float cy = xyz[(size_t)g*3+1] - newxyz[(size_t)bs*3+1];
    float cz = xyz[(size_t)g*3+2] - newxyz[(size_t)bs*3+2];
    float h = db1[c];
    h = fmaf(cx, dw1[0*COUT + c], h);
    h = fmaf(cy, dw1[1*COUT + c], h);
    h = fmaf(cz, dw1[2*COUT + c], h);
    g_buf4[(size_t)r*COUT + c] = fmaxf(h, 0.0f);
}

// ----------------- a1 = q - K + pe (in place into buf1) --------------------
__global__ void a1_kernel()
{
    size_t e = (size_t)blockIdx.x * blockDim.x + threadIdx.x;
    int bs = (int)(e >> 12);          // /(K*COUT)
    int c  = (int)(e & 255);
    g_buf1[e] = __fadd_rn(__fsub_rn(g_q[(size_t)bs*COUT + c], g_buf1[e]), g_buf3[e]);
}

// --------------- softmax over K axis (per channel) + weighted sum ----------
__global__ __launch_bounds__(256) void softmax_reduce_kernel()
{
    int bs = blockIdx.x;    // 0..8191
    int c  = threadIdx.x;   // 0..255
    size_t base = (size_t)bs * KNBR * COUT + c;
    float a[16];
    float mx = -3.4e38f;
#pragma unroll
    for (int i = 0; i < 16; i++) {
        a[i] = g_buf1[base + (size_t)i*COUT] * 0.0625f;   // /sqrt(256)
        mx = fmaxf(mx, a[i]);
    }
    float se = 0.0f;
#pragma unroll
    for (int i = 0; i < 16; i++) { a[i] = expf(a[i] - mx); se += a[i]; }
    float inv = 1.0f / se;
    float acc = 0.0f;
#pragma unroll
    for (int i = 0; i < 16; i++) {
        float vp = g_buf2[base + (size_t)i*COUT] + g_buf3[base + (size_t)i*COUT];
        acc = fmaf(a[i]*inv, vp, acc);
    }
    g_res0[(size_t)bs*COUT + c] = acc;
}

// ---------------------------- BatchNorm ------------------------------------
__global__ void bn_partial_kernel()
{
    int blk = blockIdx.x;   // 64 blocks, 128 rows each
    int c   = threadIdx.x;
    float s = 0.0f, q = 0.0f;
    for (int r = blk*128; r < blk*128 + 128; r++) {
        float x = g_res1[(size_t)r*COUT + c];
        s += x; q = fmaf(x, x, q);
    }
    g_psum[blk*COUT + c] = s;
    g_psq [blk*COUT + c] = q;
}

__global__ void bn_final_kernel(const float* __restrict__ bng, const float* __restrict__ bnb)
{
    int c = threadIdx.x;
    float s = 0.0f, q = 0.0f;
    for (int i = 0; i < 64; i++) { s += g_psum[i*COUT + c]; q += g_psq[i*COUT + c]; }
    float mean = s * (1.0f/ (float)BSR);
    float var  = fmaxf(q * (1.0f/(float)BSR) - mean*mean, 0.0f);
    float sc   = bng[c] * rsqrtf(var + 1e-5f);
    g_scale[c] = sc;
    g_shift[c] = bnb[c] - mean * sc;
}

__global__ void bn_apply_kernel(float* __restrict__ out)
{
    size_t e = (size_t)blockIdx.x * blockDim.x + threadIdx.x;
    int c = (int)(e & 255);
    out[e] = fmaxf(fmaf(g_res1[e], g_scale[c], g_shift[c]), 0.0f);
}

// ------------------------------ launch --------------------------------------
extern "C" void kernel_launch(void* const* d_in, const int* in_sizes, int n_in,
                              void* d_out, int out_size)
{
    const float* xyz    = (const float*)d_in[0];
    const float* points = (const float*)d_in[1];
    const float* wq     = (const float*)d_in[2];
    const float* wk     = (const float*)d_in[3];
    const float* wv     = (const float*)d_in[4];
    const float* dw1    = (const float*)d_in[5];
    const float* db1    = (const float*)d_in[6];
    const float* dw2    = (const float*)d_in[7];
    const float* db2    = (const float*)d_in[8];
    const float* gw1    = (const float*)d_in[9];
    const float* gb1    = (const float*)d_in[10];
    const float* gw2    = (const float*)d_in[11];
    const float* gb2    = (const float*)d_in[12];
    const float* lw     = (const float*)d_in[13];
    const float* lb     = (const float*)d_in[14];
    const float* bng    = (const float*)d_in[15];
    const float* bnb    = (const float*)d_in[16];

    float* out     = (float*)d_out;
    float* newxyz  = out;                 // [B,S,3]
    float* res_out = out + (size_t)BSR*3; // [B,S,COUT]

    void *pb1, *pb2, *pb3, *pb4, *pq, *pr0, *pr1, *pfps, *pknn;
    cudaGetSymbolAddress(&pb1, g_buf1);
    cudaGetSymbolAddress(&pb2, g_buf2);
    cudaGetSymbolAddress(&pb3, g_buf3);
    cudaGetSymbolAddress(&pb4, g_buf4);
    cudaGetSymbolAddress(&pq,  g_q);
    cudaGetSymbolAddress(&pr0, g_res0);
    cudaGetSymbolAddress(&pr1, g_res1);
    cudaGetSymbolAddress(&pfps, g_fps);
    cudaGetSymbolAddress(&pknn, g_knn);

    // 1. FPS (+ writes new_xyz to output)
    fps_kernel<<<BB, 1024>>>(xyz, newxyz);
    // 2. KNN indices
    knn_kernel<<<BSR/8, 256>>>(xyz, newxyz);
    // 3. q = gather(points, fps) @ wq
    sgemm_k<<<dim3(COUT/128, BSR/128), 256>>>(points, (const int*)pfps, wq, nullptr,
                                              (float*)pq, BSR, CIN, COUT, 0);
    // 4/5. K and V = gather(points, knn) @ wk/wv
    sgemm_k<<<dim3(COUT/128, MROWS/128), 256>>>(points, (const int*)pknn, wk, nullptr,
                                                (float*)pb1, MROWS, CIN, COUT, 0);
    sgemm_k<<<dim3(COUT/128, MROWS/128), 256>>>(points, (const int*)pknn, wv, nullptr,
                                                (float*)pb2, MROWS, CIN, COUT, 0);
    // 6. pos-enc layer 1 (3->256 relu) into buf4
    h1_kernel<<<MROWS, 256>>>(xyz, newxyz, dw1, db1);
    // 7. pos-enc layer 2: pe = h1 @ dw2 + db2 -> buf3
    sgemm_k<<<dim3(COUT/128, MROWS/128), 256>>>((const float*)pb4, nullptr, dw2, db2,
                                                (float*)pb3, MROWS, COUT, COUT, 0);
    // 8. a1 = q - K + pe (in-place buf1)
    a1_kernel<<<(MROWS*COUT)/1024, 1024>>>();
    // 9. h2 = relu(a1 @ gw1 + gb1) -> buf4
    sgemm_k<<<dim3(COUT/128, MROWS/128), 256>>>((const float*)pb1, nullptr, gw1, gb1,
                                                (float*)pb4, MROWS, COUT, COUT, 1);
    // 10. att = h2 @ gw2 + gb2 -> buf1
    sgemm_k<<<dim3(COUT/128, MROWS/128), 256>>>((const float*)pb4, nullptr, gw2, gb2,
                                                (float*)pb1, MROWS, COUT, COUT, 0);
    // 11. softmax over K + weighted sum of (V+pe) -> res0
    softmax_reduce_kernel<<<BSR, 256>>>();
    // 12. res1 = res0 @ lw + lb
    sgemm_k<<<dim3(COUT/128, BSR/128), 256>>>((const float*)pr0, nullptr, lw, lb,
                                              (float*)pr1, BSR, COUT, COUT, 0);
    // 13. BatchNorm (training stats) + ReLU -> output
    bn_partial_kernel<<<64, 256>>>();
    bn_final_kernel<<<1, 256>>>(bng, bnb);
    bn_apply_kernel<<<(BSR*COUT)/1024, 1024>>>(res_out);
}

// round 2
// speedup vs baseline: 1.7716x; 1.7716x over previous
#include <cuda_runtime.h>
#include <math.h>
#include <stdint.h>

#define BB   8
#define NN   4096
#define SS   1024
#define KNBR 16
#define CIN  128
#define COUT 256
#define MROWS (BB*SS*KNBR)   /* 131072 */
#define BSR   (BB*SS)        /* 8192  */
#define NPTS  (BB*NN)        /* 32768 */

// ---------------- static device scratch (no allocs allowed) ----------------
__device__ float g_pos [(size_t)MROWS*COUT];  // pos_enc
__device__ float g_bufA[(size_t)MROWS*COUT];  // a1 -> att
__device__ float g_bufB[(size_t)MROWS*COUT];  // h1 -> h2
__device__ float g_kall[(size_t)NPTS*COUT];
__device__ float g_vall[(size_t)NPTS*COUT];
__device__ float g_q   [(size_t)BSR*COUT];
__device__ float g_res0[(size_t)BSR*COUT];
__device__ float g_res1[(size_t)BSR*COUT];
__device__ int   g_fps [BSR];
__device__ int   g_knn [MROWS];
__device__ float g_psum[64*COUT];
__device__ float g_psq [64*COUT];
__device__ float g_scale[COUT];
__device__ float g_shift[COUT];

// ---------------------------- FPS -----------------------------------------
__global__ __launch_bounds__(1024) void fps_kernel(const float* __restrict__ xyz,
                                                   float* __restrict__ newxyz)
{
    int b   = blockIdx.x;
    int tid = threadIdx.x;
    const float* base = xyz + (size_t)b * NN * 3;

    float px[4], py[4], pz[4], dist[4];
#pragma unroll
    for (int j = 0; j < 4; j++) {
        int i = tid * 4 + j;
        px[j] = base[i*3+0]; py[j] = base[i*3+1]; pz[j] = base[i*3+2];
        dist[j] = 1e10f;
    }

    __shared__ float swv[32];
    __shared__ int   swi[32];
    __shared__ int   sfar;

    int far  = 0;
    int lane = tid & 31, wid = tid >> 5;

    for (int s = 0; s < SS; s++) {
        float cx = __ldg(base + far*3 + 0);
        float cy = __ldg(base + far*3 + 1);
        float cz = __ldg(base + far*3 + 2);
        if (tid == 0) {
            g_fps[b*SS + s] = b*NN + far;
            newxyz[((size_t)b*SS + s)*3 + 0] = cx;
            newxyz[((size_t)b*SS + s)*3 + 1] = cy;
            newxyz[((size_t)b*SS + s)*3 + 2] = cz;
        }
        float bv = -1.0f; int bi = 0;
#pragma unroll
        for (int j = 0; j < 4; j++) {
            float dx = __fsub_rn(px[j], cx);
            float dy = __fsub_rn(py[j], cy);
            float dz = __fsub_rn(pz[j], cz);
            float d  = __fadd_rn(__fadd_rn(__fmul_rn(dx,dx), __fmul_rn(dy,dy)),
                                 __fmul_rn(dz,dz));
            dist[j] = fminf(dist[j], d);
            if (dist[j] > bv) { bv = dist[j]; bi = tid*4 + j; }
        }
#pragma unroll
        for (int off = 16; off; off >>= 1) {
            float ov = __shfl_xor_sync(0xffffffffu, bv, off);
            int   oi = __shfl_xor_sync(0xffffffffu, bi, off);
            if (ov > bv || (ov == bv && oi < bi)) { bv = ov; bi = oi; }
        }
        if (lane == 0) { swv[wid] = bv; swi[wid] = bi; }
        __syncthreads();
        if (tid < 32) {
            bv = swv[tid]; bi = swi[tid];
#pragma unroll
            for (int off = 16; off; off >>= 1) {
                float ov = __shfl_xor_sync(0xffffffffu, bv, off);
                int   oi = __shfl_xor_sync(0xffffffffu, bi, off);
                if (ov > bv || (ov == bv && oi < bi)) { bv = ov; bi = oi; }
            }
            if (tid == 0) sfar = bi;
        }
        __syncthreads();
        far = sfar;
    }
}

// ---------------------------- KNN -----------------------------------------
__global__ __launch_bounds__(256) void knn_kernel(const float* __restrict__ xyz,
                                                  const float* __restrict__ newxyz)
{
    int warp = (blockIdx.x * blockDim.x + threadIdx.x) >> 5;
    int lane = threadIdx.x & 31;
    int wloc = threadIdx.x >> 5;
    int b = warp / SS;
    const float* base = xyz + (size_t)b * NN * 3;

    float nx = newxyz[(size_t)warp*3+0];
    float ny = newxyz[(size_t)warp*3+1];
    float nz = newxyz[(size_t)warp*3+2];
    float ns = fmaf(nz, nz, fmaf(ny, ny, __fmul_rn(nx, nx)));

    float v[16]; int id[16];
#pragma unroll
    for (int t = 0; t < 16; t++) { v[t] = 3.4e38f; id[t] = 0x7fffffff; }

    for (int j = lane; j < NN; j += 32) {
        float x = base[j*3+0], y = base[j*3+1], z = base[j*3+2];
        float dot = fmaf(z, nz, fmaf(y, ny, __fmul_rn(x, nx)));
        float nq  = fmaf(z, z,  fmaf(y, y,  __fmul_rn(x, x)));
        float d   = __fadd_rn(__fsub_rn(ns, __fmul_rn(2.0f, dot)), nq);
        if (d < v[15]) {
            v[15] = d; id[15] = j;
#pragma unroll
            for (int t = 15; t > 0; t--) {
                if (v[t] < v[t-1] || (v[t] == v[t-1] && id[t] < id[t-1])) {
                    float tv = v[t]; v[t] = v[t-1]; v[t-1] = tv;
                    int   ti = id[t]; id[t] = id[t-1]; id[t-1] = ti;
                } else break;
            }
        }
    }

    __shared__ float smd[8][512];
    __shared__ int   smi[8][512];
#pragma unroll
    for (int t = 0; t < 16; t++) {
        smd[wloc][lane*16 + t] = v[t];
        smi[wloc][lane*16 + t] = id[t];
    }
    __syncwarp();

    int p = 0;
    for (int t = 0; t < 16; t++) {
        float cv = (p < 16) ? smd[wloc][lane*16 + p] : 3.4e38f;
        int   ci = (p < 16) ? smi[wloc][lane*16 + p] : 0x7fffffff;
        float mv = cv; int mi = ci;
#pragma unroll
        for (int off = 16; off; off >>= 1) {
            float ov = __shfl_xor_sync(0xffffffffu, mv, off);
            int   oi = __shfl_xor_sync(0xffffffffu, mi, off);
            if (ov < mv || (ov == mv && oi < mi)) { mv = ov; mi = oi; }
        }
        if (cv == mv && ci == mi) p++;
        if (lane == 0) g_knn[(size_t)warp*16 + t] = b*NN + mi;
        __syncwarp();
    }
}

// ------------------------- cp.async helpers --------------------------------
__device__ __forceinline__ void cp16(float* s, const float* g)
{
    unsigned sa = (unsigned)__cvta_generic_to_shared(s);
    asm volatile("cp.async.ca.shared.global [%0], [%1], 16;\n" :: "r"(sa), "l"(g));
}
#define CP_COMMIT() asm volatile("cp.async.commit_group;\n")
#define CP_WAIT0()  asm volatile("cp.async.wait_group 0;\n" ::: "memory")

// ---------------- double-buffered fp32 tiled GEMM --------------------------
// C[M,N=256 tilewise] = gather(A)[M,Kd] @ W[Kd,N] (+bias)(+relu)
// optional dual-write: C2[row,col] = qv[row>>4,col] - kall[knn[row],col] + C[row,col]
__global__ __launch_bounds__(256) void sgemm_db(
    const float* __restrict__ A, const int* __restrict__ rowmap,
    const float* __restrict__ W, const float* __restrict__ bias,
    float* __restrict__ C, int Kd, int N, int relu,
    const float* __restrict__ qv, const float* __restrict__ kall,
    const int* __restrict__ knn, float* __restrict__ C2)
{
    __shared__ float As[2][16][132];
    __shared__ float Bs[2][16][128];
    __shared__ int   rmap[128];

    int tid = threadIdx.x;
    int m0  = blockIdx.y * 128;
    int n0  = blockIdx.x * 128;

    if (tid < 128) rmap[tid] = rowmap ? rowmap[m0 + tid] : (m0 + tid);
    __syncthreads();

    // A load slots: thread handles row (tid>>1), 8 floats at k-offset (tid&1)*8
    int sr = tid >> 1;
    int sc = (tid & 1) * 8;
    const float* abase = A + (size_t)rmap[sr] * Kd + sc;

    // B load slots: two 16B chunks
    int kr0 = (tid*2) >> 5,   bc0 = ((tid*2) & 31) * 4;
    int kr1 = (tid*2+1) >> 5, bc1 = ((tid*2+1) & 31) * 4;

    // ---- prologue: tile 0 ----
    float4 ar0 = *(const float4*)(abase);
    float4 ar1 = *(const float4*)(abase + 4);
    cp16(&Bs[0][kr0][bc0], W + (size_t)kr0 * N + n0 + bc0);
    cp16(&Bs[0][kr1][bc1], W + (size_t)kr1 * N + n0 + bc1);
    CP_COMMIT();
    As[0][sc+0][sr] = ar0.x; As[0][sc+1][sr] = ar0.y;
    As[0][sc+2][sr] = ar0.z; As[0][sc+3][sr] = ar0.w;
    As[0][sc+4][sr] = ar1.x; As[0][sc+5][sr] = ar1.y;
    As[0][sc+6][sr] = ar1.z; As[0][sc+7][sr] = ar1.w;
    CP_WAIT0();
    __syncthreads();

    float acc[8][8];
#pragma unroll
    for (int i = 0; i < 8; i++)
#pragma unroll
        for (int j = 0; j < 8; j++) acc[i][j] = 0.0f;

    int tx = tid & 15, ty = tid >> 4;
    int nk = Kd >> 4;

    for (int t = 0; t < nk; t++) {
        int cur = t & 1, nxt = cur ^ 1;
        bool more = (t + 1) < nk;
        if (more) {
            int k0 = (t + 1) * 16;
            ar0 = *(const float4*)(abase + k0);
            ar1 = *(const float4*)(abase + k0 + 4);
            cp16(&Bs[nxt][kr0][bc0], W + (size_t)(k0+kr0) * N + n0 + bc0);
            cp16(&Bs[nxt][kr1][bc1], W + (size_t)(k0+kr1) * N + n0 + bc1);
            CP_COMMIT();
        }
#pragma unroll
        for (int kk = 0; kk < 16; kk++) {
            float a[8], bq[8];
            *(float4*)(a)    = *(float4*)(&As[cur][kk][ty*8]);
            *(float4*)(a+4)  = *(float4*)(&As[cur][kk][ty*8+4]);
            *(float4*)(bq)   = *(float4*)(&Bs[cur][kk][tx*8]);
            *(float4*)(bq+4) = *(float4*)(&Bs[cur][kk][tx*8+4]);
#pragma unroll
            for (int i = 0; i < 8; i++)
#pragma unroll
                for (int j = 0; j < 8; j++) acc[i][j] = fmaf(a[i], bq[j], acc[i][j]);
        }
        if (more) {
            As[nxt][sc+0][sr] = ar0.x; As[nxt][sc+1][sr] = ar0.y;
            As[nxt][sc+2][sr] = ar0.z; As[nxt][sc+3][sr] = ar0.w;
            As[nxt][sc+4][sr] = ar1.x; As[nxt][sc+5][sr] = ar1.y;
            As[nxt][sc+6][sr] = ar1.z; As[nxt][sc+7][sr] = ar1.w;
            CP_WAIT0();
        }
        __syncthreads();
    }

#pragma unroll
    for (int i = 0; i < 8; i++) {
        int row = m0 + ty*8 + i;
        int kn = 0;
        const float* qrow = nullptr;
        const float* krow = nullptr;
        if (C2) {
            kn = knn[row];
            qrow = qv + (size_t)(row >> 4) * N;
            krow = kall + (size_t)kn * N;
        }
#pragma unroll
        for (int j = 0; j < 8; j += 4) {
            int col = n0 + tx*8 + j;
            float4 o;
            o.x = acc[i][j+0]; o.y = acc[i][j+1]; o.z = acc[i][j+2]; o.w = acc[i][j+3];
            if (bias) { o.x += bias[col]; o.y += bias[col+1]; o.z += bias[col+2]; o.w += bias[col+3]; }
            if (relu) { o.x = fmaxf(o.x,0.f); o.y = fmaxf(o.y,0.f); o.z = fmaxf(o.z,0.f); o.w = fmaxf(o.w,0.f); }
            *(float4*)(C + (size_t)row*N + col) = o;
            if (C2) {
                float4 a1;
                a1.x = __fadd_rn(__fsub_rn(qrow[col+0], krow[col+0]), o.x);
                a1.y = __fadd_rn(__fsub_rn(qrow[col+1], krow[col+1]), o.y);
                a1.z = __fadd_rn(__fsub_rn(qrow[col+2], krow[col+2]), o.z);
                a1.w = __fadd_rn(__fsub_rn(qrow[col+3], krow[col+3]), o.w);
                *(float4*)(C2 + (size_t)row*N + col) = a1;
            }
        }
    }
}

// ------------------ pos-enc layer 1 (3 -> 256, relu) -----------------------
__global__ void h1_kernel(const float* __restrict__ xyz, const float* __restrict__ newxyz,
                          const float* __restrict__ dw1, const float* __restrict__ db1)
{
    int r = blockIdx.x;
    int c = threadIdx.x;
    int g  = g_knn[r];
    int bs = r >> 4;
    float cx = xyz[(size_t)g*3+0] - newxyz[(size_t)bs*3+0];
    float cy = xyz[(size_t)g*3+1] - newxyz[(size_t)bs*3+1];
    float cz = xyz[(size_t)g*3+2] - newxyz[(size_t)bs*3+2];
    float h = db1[c];
    h = fmaf(cx, dw1[0*COUT + c], h);
    h = fmaf(cy, dw1[1*COUT + c], h);
    h = fmaf(cz, dw1[2*COUT + c], h);
    g_bufB[(size_t)r*COUT + c] = fmaxf(h, 0.0f);
}

// --------------- softmax over K axis + weighted sum (v gathered) -----------
__global__ __launch_bounds__(256) void softmax_reduce_kernel()
{
    int bs = blockIdx.x;
    int c  = threadIdx.x;
    __shared__ int kn[16];
    if (c < 16) kn[c] = g_knn[bs*16 + c];
    __syncthreads();

    size_t base = (size_t)bs * KNBR * COUT + c;
    float a[16];
    float mx = -3.4e38f;
#pragma unroll
    for (int i = 0; i < 16; i++) {
        a[i] = g_bufA[base + (size_t)i*COUT] * 0.0625f;
        mx = fmaxf(mx, a[i]);
    }
    float se = 0.0f;
#pragma unroll
    for (int i = 0; i < 16; i++) { a[i] = expf(a[i] - mx); se += a[i]; }
    float inv = 1.0f / se;
    float acc = 0.0f;
#pragma unroll
    for (int i = 0; i < 16; i++) {
        float vp = g_vall[(size_t)kn[i]*COUT + c] + g_pos[base + (size_t)i*COUT];
        acc = fmaf(a[i]*inv, vp, acc);
    }
    g_res0[(size_t)bs*COUT + c] = acc;
}

// ---------------------------- BatchNorm ------------------------------------
__global__ void bn_partial_kernel()
{
    int blk = blockIdx.x;
    int c   = threadIdx.x;
    float s = 0.0f, q = 0.0f;
    for (int r = blk*128; r < blk*128 + 128; r++) {
        float x = g_res1[(size_t)r*COUT + c];
        s += x; q = fmaf(x, x, q);
    }
    g_psum[blk*COUT + c] = s;
    g_psq [blk*COUT + c] = q;
}

__global__ void bn_final_kernel(const float* __restrict__ bng, const float* __restrict__ bnb)
{
    int c = threadIdx.x;
    float s = 0.0f, q = 0.0f;
    for (int i = 0; i < 64; i++) { s += g_psum[i*COUT + c]; q += g_psq[i*COUT + c]; }
    float mean = s * (1.0f/(float)BSR);
    float var  = fmaxf(q * (1.0f/(float)BSR) - mean*mean, 0.0f);
    float sc   = bng[c] * rsqrtf(var + 1e-5f);
    g_scale[c] = sc;
    g_shift[c] = bnb[c] - mean * sc;
}

__global__ void bn_apply_kernel(float* __restrict__ out)
{
    size_t e = (size_t)blockIdx.x * blockDim.x + threadIdx.x;
    int c = (int)(e & 255);
    out[e] = fmaxf(fmaf(g_res1[e], g_scale[c], g_shift[c]), 0.0f);
}

// ------------------------------ launch --------------------------------------
extern "C" void kernel_launch(void* const* d_in, const int* in_sizes, int n_in,
                              void* d_out, int out_size)
{
    const float* xyz    = (const float*)d_in[0];
    const float* points = (const float*)d_in[1];
    const float* wq     = (const float*)d_in[2];
    const float* wk     = (const float*)d_in[3];
    const float* wv     = (const float*)d_in[4];
    const float* dw1    = (const float*)d_in[5];
    const float* db1    = (const float*)d_in[6];
    const float* dw2    = (const float*)d_in[7];
    const float* db2    = (const float*)d_in[8];
    const float* gw1    = (const float*)d_in[9];
    const float* gb1    = (const float*)d_in[10];
    const float* gw2    = (const float*)d_in[11];
    const float* gb2    = (const float*)d_in[12];
    const float* lw     = (const float*)d_in[13];
    const float* lb     = (const float*)d_in[14];
    const float* bng    = (const float*)d_in[15];
    const float* bnb    = (const float*)d_in[16];

    float* out     = (float*)d_out;
    float* newxyz  = out;
    float* res_out = out + (size_t)BSR*3;

    void *ppos, *pA, *pB, *pk, *pv, *pq, *pr0, *pr1, *pfps, *pknn;
    cudaGetSymbolAddress(&ppos, g_pos);
    cudaGetSymbolAddress(&pA,   g_bufA);
    cudaGetSymbolAddress(&pB,   g_bufB);
    cudaGetSymbolAddress(&pk,   g_kall);
    cudaGetSymbolAddress(&pv,   g_vall);
    cudaGetSymbolAddress(&pq,   g_q);
    cudaGetSymbolAddress(&pr0,  g_res0);
    cudaGetSymbolAddress(&pr1,  g_res1);
    cudaGetSymbolAddress(&pfps, g_fps);
    cudaGetSymbolAddress(&pknn, g_knn);

    // 1. FPS (+ writes new_xyz)
    fps_kernel<<<BB, 1024>>>(xyz, newxyz);
    // 2. KNN indices
    knn_kernel<<<BSR/8, 256>>>(xyz, newxyz);
    // 3/4. project ALL points once: k_all / v_all  (M=32768, Kd=128)
    sgemm_db<<<dim3(COUT/128, NPTS/128), 256>>>(points, nullptr, wk, nullptr,
        (float*)pk, CIN, COUT, 0, nullptr, nullptr, nullptr, nullptr);
    sgemm_db<<<dim3(COUT/128, NPTS/128), 256>>>(points, nullptr, wv, nullptr,
        (float*)pv, CIN, COUT, 0, nullptr, nullptr, nullptr, nullptr);
    // 5. q = gather(points, fps) @ wq  (M=8192)
    sgemm_db<<<dim3(COUT/128, BSR/128), 256>>>(points, (const int*)pfps, wq, nullptr,
        (float*)pq, CIN, COUT, 0, nullptr, nullptr, nullptr, nullptr);
    // 6. pos-enc layer 1 -> bufB
    h1_kernel<<<MROWS, 256>>>(xyz, newxyz, dw1, db1);
    // 7. pos = h1 @ dw2 + db2 -> g_pos;  fused dual-write a1 = q - k_gather + pos -> bufA
    sgemm_db<<<dim3(COUT/128, MROWS/128), 256>>>((const float*)pB, nullptr, dw2, db2,
        (float*)ppos, COUT, COUT, 0,
        (const float*)pq, (const float*)pk, (const int*)pknn, (float*)pA);
    // 8. h2 = relu(a1 @ gw1 + gb1) -> bufB
    sgemm_db<<<dim3(COUT/128, MROWS/128), 256>>>((const float*)pA, nullptr, gw1, gb1,
        (float*)pB, COUT, COUT, 1, nullptr, nullptr, nullptr, nullptr);
    // 9. att = h2 @ gw2 + gb2 -> bufA
    sgemm_db<<<dim3(COUT/128, MROWS/128), 256>>>((const float*)pB, nullptr, gw2, gb2,
        (float*)pA, COUT, COUT, 0, nullptr, nullptr, nullptr, nullptr);
    // 10. softmax over K + weighted sum of (v_gather + pos) -> res0
    softmax_reduce_kernel<<<BSR, 256>>>();
    // 11. res1 = res0 @ lw + lb
    sgemm_db<<<dim3(COUT/128, BSR/128), 256>>>((const float*)pr0, nullptr, lw, lb,
        (float*)pr1, COUT, COUT, 0, nullptr, nullptr, nullptr, nullptr);
    // 12. BatchNorm (training stats) + ReLU -> output
    bn_partial_kernel<<<64, 256>>>();
    bn_final_kernel<<<1, 256>>>(bng, bnb);
    bn_apply_kernel<<<(BSR*COUT)/1024, 1024>>>(res_out);
}

// round 3
// speedup vs baseline: 1.7734x; 1.0010x over previous
#include <cuda_runtime.h>
#include <math.h>
#include <stdint.h>

#define BB   8
#define NN   4096
#define SS   1024
#define KNBR 16
#define CIN  128
#define COUT 256
#define MROWS (BB*SS*KNBR)   /* 131072 */
#define BSR   (BB*SS)        /* 8192  */
#define NPTS  (BB*NN)        /* 32768 */

// ---------------- static device scratch (no allocs allowed) ----------------
__device__ float g_pos [(size_t)MROWS*COUT];  // pos_enc
__device__ float g_bufA[(size_t)MROWS*COUT];  // a1 -> att
__device__ float g_bufB[(size_t)MROWS*COUT];  // h1 -> h2
__device__ float g_kall[(size_t)NPTS*COUT];
__device__ float g_vall[(size_t)NPTS*COUT];
__device__ float g_q   [(size_t)BSR*COUT];
__device__ float g_res0[(size_t)BSR*COUT];
__device__ float g_res1[(size_t)BSR*COUT];
__device__ int   g_fps [BSR];
__device__ int   g_knn [MROWS];
__device__ float g_psum[64*COUT];
__device__ float g_psq [64*COUT];
__device__ float g_scale[COUT];
__device__ float g_shift[COUT];

// ---------------------------- FPS -----------------------------------------
__global__ __launch_bounds__(1024) void fps_kernel(const float* __restrict__ xyz,
                                                   float* __restrict__ newxyz)
{
    int b   = blockIdx.x;
    int tid = threadIdx.x;
    const float* base = xyz + (size_t)b * NN * 3;

    float px[4], py[4], pz[4], dist[4];
#pragma unroll
    for (int j = 0; j < 4; j++) {
        int i = tid * 4 + j;
        px[j] = base[i*3+0]; py[j] = base[i*3+1]; pz[j] = base[i*3+2];
        dist[j] = 1e10f;
    }

    __shared__ float swv[32];
    __shared__ int   swi[32];
    __shared__ int   sfar;

    int far  = 0;
    int lane = tid & 31, wid = tid >> 5;

    for (int s = 0; s < SS; s++) {
        float cx = __ldg(base + far*3 + 0);
        float cy = __ldg(base + far*3 + 1);
        float cz = __ldg(base + far*3 + 2);
        if (tid == 0) {
            g_fps[b*SS + s] = b*NN + far;
            newxyz[((size_t)b*SS + s)*3 + 0] = cx;
            newxyz[((size_t)b*SS + s)*3 + 1] = cy;
            newxyz[((size_t)b*SS + s)*3 + 2] = cz;
        }
        float bv = -1.0f; int bi = 0;
#pragma unroll
        for (int j = 0; j < 4; j++) {
            float dx = __fsub_rn(px[j], cx);
            float dy = __fsub_rn(py[j], cy);
            float dz = __fsub_rn(pz[j], cz);
            float d  = __fadd_rn(__fadd_rn(__fmul_rn(dx,dx), __fmul_rn(dy,dy)),
                                 __fmul_rn(dz,dz));
            dist[j] = fminf(dist[j], d);
            if (dist[j] > bv) { bv = dist[j]; bi = tid*4 + j; }
        }
#pragma unroll
        for (int off = 16; off; off >>= 1) {
            float ov = __shfl_xor_sync(0xffffffffu, bv, off);
            int   oi = __shfl_xor_sync(0xffffffffu, bi, off);
            if (ov > bv || (ov == bv && oi < bi)) { bv = ov; bi = oi; }
        }
        if (lane == 0) { swv[wid] = bv; swi[wid] = bi; }
        __syncthreads();
        if (tid < 32) {
            bv = swv[tid]; bi = swi[tid];
#pragma unroll
            for (int off = 16; off; off >>= 1) {
                float ov = __shfl_xor_sync(0xffffffffu, bv, off);
                int   oi = __shfl_xor_sync(0xffffffffu, bi, off);
                if (ov > bv || (ov == bv && oi < bi)) { bv = ov; bi = oi; }
            }
            if (tid == 0) sfar = bi;
        }
        __syncthreads();
        far = sfar;
    }
}

// ---------------------------- KNN -----------------------------------------
__global__ __launch_bounds__(256) void knn_kernel(const float* __restrict__ xyz,
                                                  const float* __restrict__ newxyz)
{
    int warp = (blockIdx.x * blockDim.x + threadIdx.x) >> 5;
    int lane = threadIdx.x & 31;
    int wloc = threadIdx.x >> 5;
    int b = warp / SS;
    const float* base = xyz + (size_t)b * NN * 3;

    float nx = newxyz[(size_t)warp*3+0];
    float ny = newxyz[(size_t)warp*3+1];
    float nz = newxyz[(size_t)warp*3+2];
    float ns = fmaf(nz, nz, fmaf(ny, ny, __fmul_rn(nx, nx)));

    float v[16]; int id[16];
#pragma unroll
    for (int t = 0; t < 16; t++) { v[t] = 3.4e38f; id[t] = 0x7fffffff; }

    for (int j = lane; j < NN; j += 32) {
        float x = base[j*3+0], y = base[j*3+1], z = base[j*3+2];
        float dot = fmaf(z, nz, fmaf(y, ny, __fmul_rn(x, nx)));
        float nq  = fmaf(z, z,  fmaf(y, y,  __fmul_rn(x, x)));
        float d   = __fadd_rn(__fsub_rn(ns, __fmul_rn(2.0f, dot)), nq);
        if (d < v[15]) {
            v[15] = d; id[15] = j;
#pragma unroll
            for (int t = 15; t > 0; t--) {
                if (v[t] < v[t-1] || (v[t] == v[t-1] && id[t] < id[t-1])) {
                    float tv = v[t]; v[t] = v[t-1]; v[t-1] = tv;
                    int   ti = id[t]; id[t] = id[t-1]; id[t-1] = ti;
                } else break;
            }
        }
    }

    __shared__ float smd[8][512];
    __shared__ int   smi[8][512];
#pragma unroll
    for (int t = 0; t < 16; t++) {
        smd[wloc][lane*16 + t] = v[t];
        smi[wloc][lane*16 + t] = id[t];
    }
    __syncwarp();

    int p = 0;
    for (int t = 0; t < 16; t++) {
        float cv = (p < 16) ? smd[wloc][lane*16 + p] : 3.4e38f;
        int   ci = (p < 16) ? smi[wloc][lane*16 + p] : 0x7fffffff;
        float mv = cv; int mi = ci;
#pragma unroll
        for (int off = 16; off; off >>= 1) {
            float ov = __shfl_xor_sync(0xffffffffu, mv, off);
            int   oi = __shfl_xor_sync(0xffffffffu, mi, off);
            if (ov < mv || (ov == mv && oi < mi)) { mv = ov; mi = oi; }
        }
        if (cv == mv && ci == mi) p++;
        if (lane == 0) g_knn[(size_t)warp*16 + t] = b*NN + mi;
        __syncwarp();
    }
}

// ------------------------- cp.async helpers --------------------------------
__device__ __forceinline__ void cp16(float* s, const float* g)
{
    unsigned sa = (unsigned)__cvta_generic_to_shared(s);
    asm volatile("cp.async.ca.shared.global [%0], [%1], 16;\n" :: "r"(sa), "l"(g));
}
#define CP_COMMIT() asm volatile("cp.async.commit_group;\n")
#define CP_WAIT0()  asm volatile("cp.async.wait_group 0;\n" ::: "memory")

// ---------------- double-buffered fp32 tiled GEMM --------------------------
// C[M,N=256 tilewise] = gather(A)[M,Kd] @ W[Kd,N] (+bias)(+relu)
// optional dual-write: C2[row,col] = qv[row>>4,col] - kall[knn[row],col] + C[row,col]
__global__ __launch_bounds__(256) void sgemm_db(
    const float* __restrict__ A, const int* __restrict__ rowmap,
    const float* __restrict__ W, const float* __restrict__ bias,
    float* __restrict__ C, int Kd, int N, int relu,
    const float* __restrict__ qv, const float* __restrict__ kall,
    const int* __restrict__ knn, float* __restrict__ C2)
{
    __shared__ float As[2][16][132];
    __shared__ float Bs[2][16][128];
    __shared__ int   rmap[128];

    int tid = threadIdx.x;
    int m0  = blockIdx.y * 128;
    int n0  = blockIdx.x * 128;

    if (tid < 128) rmap[tid] = rowmap ? rowmap[m0 + tid] : (m0 + tid);
    __syncthreads();

    // A load slots: thread handles row (tid>>1), 8 floats at k-offset (tid&1)*8
    int sr = tid >> 1;
    int sc = (tid & 1) * 8;
    const float* abase = A + (size_t)rmap[sr] * Kd + sc;

    // B load slots: two 16B chunks
    int kr0 = (tid*2) >> 5,   bc0 = ((tid*2) & 31) * 4;
    int kr1 = (tid*2+1) >> 5, bc1 = ((tid*2+1) & 31) * 4;

    // ---- prologue: tile 0 ----
    float4 ar0 = *(const float4*)(abase);
    float4 ar1 = *(const float4*)(abase + 4);
    cp16(&Bs[0][kr0][bc0], W + (size_t)kr0 * N + n0 + bc0);
    cp16(&Bs[0][kr1][bc1], W + (size_t)kr1 * N + n0 + bc1);
    CP_COMMIT();
    As[0][sc+0][sr] = ar0.x; As[0][sc+1][sr] = ar0.y;
    As[0][sc+2][sr] = ar0.z; As[0][sc+3][sr] = ar0.w;
    As[0][sc+4][sr] = ar1.x; As[0][sc+5][sr] = ar1.y;
    As[0][sc+6][sr] = ar1.z; As[0][sc+7][sr] = ar1.w;
    CP_WAIT0();
    __syncthreads();

    float acc[8][8];
#pragma unroll
    for (int i = 0; i < 8; i++)
#pragma unroll
        for (int j = 0; j < 8; j++) acc[i][j] = 0.0f;

    int tx = tid & 15, ty = tid >> 4;
    int nk = Kd >> 4;

    for (int t = 0; t < nk; t++) {
        int cur = t & 1, nxt = cur ^ 1;
        bool more = (t + 1) < nk;
        if (more) {
            int k0 = (t + 1) * 16;
            ar0 = *(const float4*)(abase + k0);
            ar1 = *(const float4*)(abase + k0 + 4);
            cp16(&Bs[nxt][kr0][bc0], W + (size_t)(k0+kr0) * N + n0 + bc0);
            cp16(&Bs[nxt][kr1][bc1], W + (size_t)(k0+kr1) * N + n0 + bc1);
            CP_COMMIT();
        }
#pragma unroll
        for (int kk = 0; kk < 16; kk++) {
            float a[8], bq[8];
            *(float4*)(a)    = *(float4*)(&As[cur][kk][ty*8]);
            *(float4*)(a+4)  = *(float4*)(&As[cur][kk][ty*8+4]);
            *(float4*)(bq)   = *(float4*)(&Bs[cur][kk][tx*8]);
            *(float4*)(bq+4) = *(float4*)(&Bs[cur][kk][tx*8+4]);
#pragma unroll
            for (int i = 0; i < 8; i++)
#pragma unroll
                for (int j = 0; j < 8; j++) acc[i][j] = fmaf(a[i], bq[j], acc[i][j]);
        }
        if (more) {
            As[nxt][sc+0][sr] = ar0.x; As[nxt][sc+1][sr] = ar0.y;
            As[nxt][sc+2][sr] = ar0.z; As[nxt][sc+3][sr] = ar0.w;
            As[nxt][sc+4][sr] = ar1.x; As[nxt][sc+5][sr] = ar1.y;
            As[nxt][sc+6][sr] = ar1.z; As[nxt][sc+7][sr] = ar1.w;
            CP_WAIT0();
        }
        __syncthreads();
    }

#pragma unroll
    for (int i = 0; i < 8; i++) {
        int row = m0 + ty*8 + i;
        int kn = 0;
        const float* qrow = nullptr;
        const float* krow = nullptr;
        if (C2) {
            kn = knn[row];
            qrow = qv + (size_t)(row >> 4) * N;
            krow = kall + (size_t)kn * N;
        }
#pragma unroll
        for (int j = 0; j < 8; j += 4) {
            int col = n0 + tx*8 + j;
            float4 o;
            o.x = acc[i][j+0]; o.y = acc[i][j+1]; o.z = acc[i][j+2]; o.w = acc[i][j+3];
            if (bias) { o.x += bias[col]; o.y += bias[col+1]; o.z += bias[col+2]; o.w += bias[col+3]; }
            if (relu) { o.x = fmaxf(o.x,0.f); o.y = fmaxf(o.y,0.f); o.z = fmaxf(o.z,0.f); o.w = fmaxf(o.w,0.f); }
            *(float4*)(C + (size_t)row*N + col) = o;
            if (C2) {
                float4 a1;
                a1.x = __fadd_rn(__fsub_rn(qrow[col+0], krow[col+0]), o.x);
                a1.y = __fadd_rn(__fsub_rn(qrow[col+1], krow[col+1]), o.y);
                a1.z = __fadd_rn(__fsub_rn(qrow[col+2], krow[col+2]), o.z);
                a1.w = __fadd_rn(__fsub_rn(qrow[col+3], krow[col+3]), o.w);
                *(float4*)(C2 + (size_t)row*N + col) = a1;
            }
        }
    }
}

// ------------------ pos-enc layer 1 (3 -> 256, relu) -----------------------
__global__ void h1_kernel(const float* __restrict__ xyz, const float* __restrict__ newxyz,
                          const float* __restrict__ dw1, const float* __restrict__ db1)
{
    int r = blockIdx.x;
    int c = threadIdx.x;
    int g  = g_knn[r];
    int bs = r >> 4;
    float cx = xyz[(size_t)g*3+0] - newxyz[(size_t)bs*3+0];
    float cy = xyz[(size_t)g*3+1] - newxyz[(size_t)bs*3+1];
    float cz = xyz[(size_t)g*3+2] - newxyz[(size_t)bs*3+2];
    float h = db1[c];
    h = fmaf(cx, dw1[0*COUT + c], h);
    h = fmaf(cy, dw1[1*COUT + c], h);
    h = fmaf(cz, dw1[2*COUT + c], h);
    g_bufB[(size_t)r*COUT + c] = fmaxf(h, 0.0f);
}

// --------------- softmax over K axis + weighted sum (v gathered) -----------
__global__ __launch_bounds__(256) void softmax_reduce_kernel()
{
    int bs = blockIdx.x;
    int c  = threadIdx.x;
    __shared__ int kn[16];
    if (c < 16) kn[c] = g_knn[bs*16 + c];
    __syncthreads();

    size_t base = (size_t)bs * KNBR * COUT + c;
    float a[16];
    float mx = -3.4e38f;
#pragma unroll
    for (int i = 0; i < 16; i++) {
        a[i] = g_bufA[base + (size_t)i*COUT] * 0.0625f;
        mx = fmaxf(mx, a[i]);
    }
    float se = 0.0f;
#pragma unroll
    for (int i = 0; i < 16; i++) { a[i] = expf(a[i] - mx); se += a[i]; }
    float inv = 1.0f / se;
    float acc = 0.0f;
#pragma unroll
    for (int i = 0; i < 16; i++) {
        float vp = g_vall[(size_t)kn[i]*COUT + c] + g_pos[base + (size_t)i*COUT];
        acc = fmaf(a[i]*inv, vp, acc);
    }
    g_res0[(size_t)bs*COUT + c] = acc;
}

// ---------------------------- BatchNorm ------------------------------------
__global__ void bn_partial_kernel()
{
    int blk = blockIdx.x;
    int c   = threadIdx.x;
    float s = 0.0f, q = 0.0f;
    for (int r = blk*128; r < blk*128 + 128; r++) {
        float x = g_res1[(size_t)r*COUT + c];
        s += x; q = fmaf(x, x, q);
    }
    g_psum[blk*COUT + c] = s;
    g_psq [blk*COUT + c] = q;
}

__global__ void bn_final_kernel(const float* __restrict__ bng, const float* __restrict__ bnb)
{
    int c = threadIdx.x;
    float s = 0.0f, q = 0.0f;
    for (int i = 0; i < 64; i++) { s += g_psum[i*COUT + c]; q += g_psq[i*COUT + c]; }
    float mean = s * (1.0f/(float)BSR);
    float var  = fmaxf(q * (1.0f/(float)BSR) - mean*mean, 0.0f);
    float sc   = bng[c] * rsqrtf(var + 1e-5f);
    g_scale[c] = sc;
    g_shift[c] = bnb[c] - mean * sc;
}

__global__ void bn_apply_kernel(float* __restrict__ out)
{
    size_t e = (size_t)blockIdx.x * blockDim.x + threadIdx.x;
    int c = (int)(e & 255);
    out[e] = fmaxf(fmaf(g_res1[e], g_scale[c], g_shift[c]), 0.0f);
}

// ------------------------------ launch --------------------------------------
extern "C" void kernel_launch(void* const* d_in, const int* in_sizes, int n_in,
                              void* d_out, int out_size)
{
    const float* xyz    = (const float*)d_in[0];
    const float* points = (const float*)d_in[1];
    const float* wq     = (const float*)d_in[2];
    const float* wk     = (const float*)d_in[3];
    const float* wv     = (const float*)d_in[4];
    const float* dw1    = (const float*)d_in[5];
    const float* db1    = (const float*)d_in[6];
    const float* dw2    = (const float*)d_in[7];
    const float* db2    = (const float*)d_in[8];
    const float* gw1    = (const float*)d_in[9];
    const float* gb1    = (const float*)d_in[10];
    const float* gw2    = (const float*)d_in[11];
    const float* gb2    = (const float*)d_in[12];
    const float* lw     = (const float*)d_in[13];
    const float* lb     = (const float*)d_in[14];
    const float* bng    = (const float*)d_in[15];
    const float* bnb    = (const float*)d_in[16];

    float* out     = (float*)d_out;
    float* newxyz  = out;
    float* res_out = out + (size_t)BSR*3;

    void *ppos, *pA, *pB, *pk, *pv, *pq, *pr0, *pr1, *pfps, *pknn;
    cudaGetSymbolAddress(&ppos, g_pos);
    cudaGetSymbolAddress(&pA,   g_bufA);
    cudaGetSymbolAddress(&pB,   g_bufB);
    cudaGetSymbolAddress(&pk,   g_kall);
    cudaGetSymbolAddress(&pv,   g_vall);
    cudaGetSymbolAddress(&pq,   g_q);
    cudaGetSymbolAddress(&pr0,  g_res0);
    cudaGetSymbolAddress(&pr1,  g_res1);
    cudaGetSymbolAddress(&pfps, g_fps);
    cudaGetSymbolAddress(&pknn, g_knn);

    // 1. FPS (+ writes new_xyz)
    fps_kernel<<<BB, 1024>>>(xyz, newxyz);
    // 2. KNN indices
    knn_kernel<<<BSR/8, 256>>>(xyz, newxyz);
    // 3/4. project ALL points once: k_all / v_all  (M=32768, Kd=128)
    sgemm_db<<<dim3(COUT/128, NPTS/128), 256>>>(points, nullptr, wk, nullptr,
        (float*)pk, CIN, COUT, 0, nullptr, nullptr, nullptr, nullptr);
    sgemm_db<<<dim3(COUT/128, NPTS/128), 256>>>(points, nullptr, wv, nullptr,
        (float*)pv, CIN, COUT, 0, nullptr, nullptr, nullptr, nullptr);
    // 5. q = gather(points, fps) @ wq  (M=8192)
    sgemm_db<<<dim3(COUT/128, BSR/128), 256>>>(points, (const int*)pfps, wq, nullptr,
        (float*)pq, CIN, COUT, 0, nullptr, nullptr, nullptr, nullptr);
    // 6. pos-enc layer 1 -> bufB
    h1_kernel<<<MROWS, 256>>>(xyz, newxyz, dw1, db1);
    // 7. pos = h1 @ dw2 + db2 -> g_pos;  fused dual-write a1 = q - k_gather + pos -> bufA
    sgemm_db<<<dim3(COUT/128, MROWS/128), 256>>>((const float*)pB, nullptr, dw2, db2,
        (float*)ppos, COUT, COUT, 0,
        (const float*)pq, (const float*)pk, (const int*)pknn, (float*)pA);
    // 8. h2 = relu(a1 @ gw1 + gb1) -> bufB
    sgemm_db<<<dim3(COUT/128, MROWS/128), 256>>>((const float*)pA, nullptr, gw1, gb1,
        (float*)pB, COUT, COUT, 1, nullptr, nullptr, nullptr, nullptr);
    // 9. att = h2 @ gw2 + gb2 -> bufA
    sgemm_db<<<dim3(COUT/128, MROWS/128), 256>>>((const float*)pB, nullptr, gw2, gb2,
        (float*)pA, COUT, COUT, 0, nullptr, nullptr, nullptr, nullptr);
    // 10. softmax over K + weighted sum of (v_gather + pos) -> res0
    softmax_reduce_kernel<<<BSR, 256>>>();
    // 11. res1 = res0 @ lw + lb
    sgemm_db<<<dim3(COUT/128, BSR/128), 256>>>((const float*)pr0, nullptr, lw, lb,
        (float*)pr1, COUT, COUT, 0, nullptr, nullptr, nullptr, nullptr);
    // 12. BatchNorm (training stats) + ReLU -> output
    bn_partial_kernel<<<64, 256>>>();
    bn_final_kernel<<<1, 256>>>(bng, bnb);
    bn_apply_kernel<<<(BSR*COUT)/1024, 1024>>>(res_out);
}